// round 6
// baseline (speedup 1.0000x reference)
#include <cuda_runtime.h>
#include <math.h>
#include <stdint.h>

#define D_MODEL 1024
#define SEQ     2048
#define NHEADS  16
#define HDIM    64
#define BATCH   4
#define MTOT    (BATCH*SEQ)

// Scratch (allocation-free rule: __device__ globals)
__device__ float g_Q[(size_t)MTOT * D_MODEL];
__device__ float g_K[(size_t)MTOT * D_MODEL];
__device__ float g_V[(size_t)MTOT * D_MODEL];
__device__ float g_A[(size_t)MTOT * D_MODEL];
__device__ float2 g_RT[(size_t)SEQ * 512];   // RoPE cos/sin table

// ---------------------------------------------------------------------------
// helpers
// ---------------------------------------------------------------------------
__device__ __forceinline__ unsigned to_tf32(float x) {
    unsigned r; asm("cvt.rna.tf32.f32 %0, %1;" : "=r"(r) : "f"(x)); return r;
}
__device__ __forceinline__ void mma_tf32(float* d, const unsigned* a, const unsigned* b) {
    asm volatile(
        "mma.sync.aligned.m16n8k8.row.col.f32.tf32.tf32.f32 "
        "{%0,%1,%2,%3}, {%4,%5,%6,%7}, {%8,%9}, {%0,%1,%2,%3};\n"
        : "+f"(d[0]), "+f"(d[1]), "+f"(d[2]), "+f"(d[3])
        : "r"(a[0]), "r"(a[1]), "r"(a[2]), "r"(a[3]), "r"(b[0]), "r"(b[1]));
}
__device__ __forceinline__ uint32_t smem_u32(const void* p) {
    uint32_t a;
    asm("{ .reg .u64 t; cvta.to.shared.u64 t, %1; cvt.u32.u64 %0, t; }" : "=r"(a) : "l"(p));
    return a;
}
__device__ __forceinline__ void cpa16(uint32_t dst, const void* src) {
    asm volatile("cp.async.cg.shared.global [%0], [%1], 16;" :: "r"(dst), "l"(src));
}
#define CPA_COMMIT() asm volatile("cp.async.commit_group;" ::: "memory")
#define CPA_WAIT(n)  asm volatile("cp.async.wait_group %0;" :: "n"(n) : "memory")

// exp2 on the FMA pipe (no MUFU). Valid for x <= ~0; clamps at -125.
__device__ __forceinline__ float fexp2(float x) {
    x = fmaxf(x, -125.f);
    float t = x + 12582912.f;
    int  ix = __float_as_int(t) - 0x4B400000;
    float f = x - (t - 12582912.f);
    float p = 1.3333558146e-3f;
    p = fmaf(p, f, 9.6181291076e-3f);
    p = fmaf(p, f, 5.5504108665e-2f);
    p = fmaf(p, f, 2.4022650696e-1f);
    p = fmaf(p, f, 6.9314718056e-1f);
    p = fmaf(p, f, 1.0f);
    return p * __int_as_float((ix + 127) << 23);
}

// ===========================================================================
// RoPE table
// ===========================================================================
__global__ __launch_bounds__(256) void rope_table() {
    const int i = blockIdx.x * 256 + threadIdx.x;
    const int pos = i >> 9, p = i & 511;
    const float NEG_L2B = -0.02595256324130752f;
    const float fr = exp2f((float)p * NEG_L2B);
    float s, c; sincosf((float)pos * fr, &s, &c);
    g_RT[i] = make_float2(c, s);
}

// ===========================================================================
// tf32 GEMM (mma.sync), cp.async 4-stage pipeline.
// CTA 128x128, BK=16. 8 warps (2m x 4n), warp tile 64x32, 4x4 mma tiles.
// smem holds raw fp32; cvt->tf32 at fragment load.
// ===========================================================================
#define GBM 128
#define GBN 128
#define GBK 16
#define GAST 20
#define GBST 136
#define GASZ (GBM*GAST)
#define GBSZ (GBK*GBST)
#define GSTG 4
#define GEMM_SMEM (GSTG*(GASZ+GBSZ)*4)   // 75776 B
#define NCHUNK (D_MODEL/GBK)             // 64

__global__ __launch_bounds__(256) void gemm_cpa(
    const float* __restrict__ A, const float* __restrict__ W,
    const float* __restrict__ bias, float* __restrict__ C, int applyRope)
{
    extern __shared__ float smf[];
    float* As = smf;
    float* Bs = smf + GSTG*GASZ;
    const uint32_t s_as = smem_u32(As);
    const uint32_t s_bs = smem_u32(Bs);

    const int t = threadIdx.x, lane = t & 31, wid = t >> 5;
    const int lg = lane >> 2, lc = lane & 3;
    const int wm = (wid >> 2) * 64, wn = (wid & 3) * 32;
    const int m0 = blockIdx.y * GBM, n0 = blockIdx.x * GBN;

    const int a_m  = t >> 2,  a_sg = t & 3;
    const int b_k  = t >> 5,  b_sg = t & 31;

    const float* Asrc = A + (size_t)(m0 + a_m) * D_MODEL + 4*a_sg;
    const float* Bsrc = W + (size_t)b_k * D_MODEL + n0 + 4*b_sg;

#define GEMM_LOAD(cc, buf) do { \
    const int k0_ = (cc) * GBK; \
    const uint32_t ab = s_as + (buf)*GASZ*4; \
    const uint32_t bb = s_bs + (buf)*GBSZ*4; \
    cpa16(ab + (uint32_t)((a_m      )*GAST + a_sg*4)*4, Asrc + k0_); \
    cpa16(ab + (uint32_t)((a_m + 64 )*GAST + a_sg*4)*4, Asrc + k0_ + (size_t)64*D_MODEL); \
    cpa16(bb + (uint32_t)((b_k      )*GBST + b_sg*4)*4, Bsrc + (size_t)(k0_    )*D_MODEL); \
    cpa16(bb + (uint32_t)((b_k + 8  )*GBST + b_sg*4)*4, Bsrc + (size_t)(k0_ + 8)*D_MODEL); \
} while (0)

    float acc[4][4][4];
#pragma unroll
    for (int i = 0; i < 4; i++)
#pragma unroll
        for (int j = 0; j < 4; j++)
#pragma unroll
            for (int k = 0; k < 4; k++) acc[i][j][k] = 0.f;

    GEMM_LOAD(0, 0); CPA_COMMIT();
    GEMM_LOAD(1, 1); CPA_COMMIT();
    GEMM_LOAD(2, 2); CPA_COMMIT();

#pragma unroll 1
    for (int c = 0; c < NCHUNK; c++) {
        CPA_WAIT(2);
        __syncthreads();
        if (c + 3 < NCHUNK) GEMM_LOAD(c + 3, (c + 3) & 3);
        CPA_COMMIT();

        const float* Ab = As + (c & 3)*GASZ;
        const float* Bb = Bs + (c & 3)*GBSZ;
#pragma unroll
        for (int ks = 0; ks < 2; ks++) {
            unsigned af[4][4], bf[4][2];
#pragma unroll
            for (int mt = 0; mt < 4; mt++) {
                const float* ap = Ab + (wm + mt*16 + lg)*GAST + ks*8 + lc;
                af[mt][0] = to_tf32(ap[0]);
                af[mt][1] = to_tf32(ap[8*GAST]);
                af[mt][2] = to_tf32(ap[4]);
                af[mt][3] = to_tf32(ap[8*GAST + 4]);
            }
#pragma unroll
            for (int nt = 0; nt < 4; nt++) {
                const float* bp = Bb + (ks*8 + lc)*GBST + wn + nt*8 + lg;
                bf[nt][0] = to_tf32(bp[0]);
                bf[nt][1] = to_tf32(bp[4*GBST]);
            }
#pragma unroll
            for (int mt = 0; mt < 4; mt++)
#pragma unroll
                for (int nt = 0; nt < 4; nt++)
                    mma_tf32(acc[mt][nt], af[mt], bf[nt]);
        }
    }

    // Epilogue: bias + optional RoPE (table-based).
#pragma unroll
    for (int nt = 0; nt < 4; nt++) {
        const int col = n0 + wn + nt*8 + 2*lc;
        const float b0 = bias[col], b1 = bias[col + 1];
        const float2* rt = &g_RT[(size_t)(col >> 1)];
#pragma unroll
        for (int mt = 0; mt < 4; mt++) {
#pragma unroll
            for (int hh = 0; hh < 2; hh++) {
                const int row = m0 + wm + mt*16 + lg + 8*hh;
                float v0 = acc[mt][nt][2*hh + 0] + b0;
                float v1 = acc[mt][nt][2*hh + 1] + b1;
                if (applyRope) {
                    const float2 cs = rt[(size_t)(row & (SEQ-1)) * 512];
                    const float r0 = v0 * cs.x - v1 * cs.y;
                    v1 = v0 * cs.y + v1 * cs.x;
                    v0 = r0;
                }
                *(float2*)(C + (size_t)row * D_MODEL + col) = make_float2(v0, v1);
            }
        }
    }
}

// ===========================================================================
// Flash attention v4 (fixed loader): tf32 mma.sync + cp.async double-buffered
// K/V, P via warp shuffle. BM=128, BN=64, 8 warps.
// ===========================================================================
#define FBM 128
#define FBN 64
#define QST 68
#define KST 68
#define VST 72
#define QSZ (FBM*QST)
#define KSZ (FBN*KST)
#define VSZ (FBN*VST)
#define FLASH_SMEM ((QSZ + 2*KSZ + 2*VSZ)*4)    // 106496 B

__global__ __launch_bounds__(256, 2) void flash4(
    const float* __restrict__ Q, const float* __restrict__ K,
    const float* __restrict__ V, float* __restrict__ O)
{
    extern __shared__ float sm[];
    float* Qs = sm;                 // [128][QST] raw fp32
    float* Ks = Qs + QSZ;           // [2][64][KST]
    float* Vs = Ks + 2*KSZ;         // [2][64][VST]
    const uint32_t s_q = smem_u32(Qs);
    const uint32_t s_k = smem_u32(Ks);
    const uint32_t s_v = smem_u32(Vs);

    const int t = threadIdx.x, lane = t & 31, w = t >> 5;
    const int lg = lane >> 2, lc = lane & 3;
    const int wm = w * 16;
    const int qt = blockIdx.x, h = blockIdx.y, b = blockIdx.z;
    const int q0 = qt * FBM;

    const float* Qb = Q + (size_t)b * SEQ * D_MODEL + (size_t)h * HDIM;
    const float* Kb = K + (size_t)b * SEQ * D_MODEL + (size_t)h * HDIM;
    const float* Vb = V + (size_t)b * SEQ * D_MODEL + (size_t)h * HDIM;
    float*       Ob = O + (size_t)b * SEQ * D_MODEL + (size_t)h * HDIM;

    // loader: 4 threads per row; each thread covers segs l_s0+4i (i=0..3)
    // -> full 64-float rows (16 x 16B segments).
    const int l_r = t >> 2, l_s0 = t & 3;

#define KV_LOAD(kt_, buf) do { \
    const int k0_ = (kt_) * FBN; \
    const float* krow_ = Kb + (size_t)(k0_ + l_r) * D_MODEL; \
    const float* vrow_ = Vb + (size_t)(k0_ + l_r) * D_MODEL; \
    _Pragma("unroll") \
    for (int i_ = 0; i_ < 4; i_++) { \
        const int sg_ = l_s0 + 4*i_; \
        cpa16(s_k + (uint32_t)((buf)*KSZ + l_r*KST + sg_*4)*4, krow_ + 4*sg_); \
        cpa16(s_v + (uint32_t)((buf)*VSZ + l_r*VST + sg_*4)*4, vrow_ + 4*sg_); \
    } \
} while (0)

    // prologue: full Q tile (128 rows x 64 floats) + KV tile 0
    {
        const float* q0p = Qb + (size_t)(q0 + l_r     ) * D_MODEL;
        const float* q1p = Qb + (size_t)(q0 + l_r + 64) * D_MODEL;
#pragma unroll
        for (int i = 0; i < 4; i++) {
            const int sg = l_s0 + 4*i;
            cpa16(s_q + (uint32_t)((l_r     )*QST + sg*4)*4, q0p + 4*sg);
            cpa16(s_q + (uint32_t)((l_r + 64)*QST + sg*4)*4, q1p + 4*sg);
        }
    }
    KV_LOAD(0, 0);
    CPA_COMMIT();

    float accO[8][4];
#pragma unroll
    for (int i = 0; i < 8; i++)
#pragma unroll
        for (int j = 0; j < 4; j++) accO[i][j] = 0.f;
    float m0 = -1e30f, m1 = -1e30f, l0 = 0.f, l1 = 0.f;

    const float QSC = 0.125f * 1.4426950408889634f;   // 1/sqrt(64) * log2(e)
    const int ntiles = 2*qt + 2;

#pragma unroll 1
    for (int kt = 0; kt < ntiles; kt++) {
        const int k0 = kt * FBN;
        const int buf = kt & 1;
        CPA_WAIT(0);
        __syncthreads();
        if (kt + 1 < ntiles) KV_LOAD(kt + 1, buf ^ 1);
        CPA_COMMIT();

        if (k0 <= q0 + wm + 15) {
            const float* Kt = Ks + buf*KSZ;
            const float* Vt = Vs + buf*VSZ;

            // ---- S = Q K^T ----
            float accS[8][4];
#pragma unroll
            for (int i = 0; i < 8; i++)
#pragma unroll
                for (int j = 0; j < 4; j++) accS[i][j] = 0.f;
#pragma unroll
            for (int k8 = 0; k8 < 8; k8++) {
                unsigned a[4];
                const float* ap = Qs + (wm + lg)*QST + k8*8 + lc;
                a[0] = to_tf32(ap[0]);
                a[1] = to_tf32(ap[8*QST]);
                a[2] = to_tf32(ap[4]);
                a[3] = to_tf32(ap[8*QST + 4]);
#pragma unroll
                for (int nt = 0; nt < 8; nt++) {
                    unsigned bfr[2];
                    const float* bp = Kt + (nt*8 + lg)*KST + k8*8 + lc;
                    bfr[0] = to_tf32(bp[0]);
                    bfr[1] = to_tf32(bp[4]);
                    mma_tf32(accS[nt], a, bfr);
                }
            }

            // scale into base-2 domain
#pragma unroll
            for (int nt = 0; nt < 8; nt++) {
                accS[nt][0] *= QSC; accS[nt][1] *= QSC;
                accS[nt][2] *= QSC; accS[nt][3] *= QSC;
            }

            // ---- causal mask (diagonal tiles only) ----
            if (k0 + 63 > q0 + wm) {
                const int r0g = q0 + wm + lg, r1g = r0g + 8;
#pragma unroll
                for (int nt = 0; nt < 8; nt++) {
                    const int c = k0 + nt*8 + 2*lc;
                    if (c     > r0g) accS[nt][0] = -1e30f;
                    if (c + 1 > r0g) accS[nt][1] = -1e30f;
                    if (c     > r1g) accS[nt][2] = -1e30f;
                    if (c + 1 > r1g) accS[nt][3] = -1e30f;
                }
            }

            // ---- online softmax ----
            float mx0 = -1e30f, mx1 = -1e30f;
#pragma unroll
            for (int nt = 0; nt < 8; nt++) {
                mx0 = fmaxf(mx0, fmaxf(accS[nt][0], accS[nt][1]));
                mx1 = fmaxf(mx1, fmaxf(accS[nt][2], accS[nt][3]));
            }
            mx0 = fmaxf(mx0, __shfl_xor_sync(0xffffffffu, mx0, 1));
            mx0 = fmaxf(mx0, __shfl_xor_sync(0xffffffffu, mx0, 2));
            mx1 = fmaxf(mx1, __shfl_xor_sync(0xffffffffu, mx1, 1));
            mx1 = fmaxf(mx1, __shfl_xor_sync(0xffffffffu, mx1, 2));
            const float mn0 = fmaxf(m0, mx0), mn1 = fmaxf(m1, mx1);
            const float al0 = fexp2(m0 - mn0), al1 = fexp2(m1 - mn1);
            float s0 = 0.f, s1 = 0.f;
#pragma unroll
            for (int nt = 0; nt < 8; nt++) {
                accS[nt][0] = fexp2(accS[nt][0] - mn0);
                accS[nt][1] = fexp2(accS[nt][1] - mn0);
                accS[nt][2] = fexp2(accS[nt][2] - mn1);
                accS[nt][3] = fexp2(accS[nt][3] - mn1);
                s0 += accS[nt][0] + accS[nt][1];
                s1 += accS[nt][2] + accS[nt][3];
            }
            s0 += __shfl_xor_sync(0xffffffffu, s0, 1);
            s0 += __shfl_xor_sync(0xffffffffu, s0, 2);
            s1 += __shfl_xor_sync(0xffffffffu, s1, 1);
            s1 += __shfl_xor_sync(0xffffffffu, s1, 2);
            l0 = l0*al0 + s0;  l1 = l1*al1 + s1;
            m0 = mn0;          m1 = mn1;
#pragma unroll
            for (int nt = 0; nt < 8; nt++) {
                accO[nt][0] *= al0; accO[nt][1] *= al0;
                accO[nt][2] *= al1; accO[nt][3] *= al1;
            }

            // ---- O += P V : P fragments via warp shuffle ----
            const int L1 = (lg << 2) | (lc >> 1);
            const bool odd = (lc & 1);
#pragma unroll
            for (int k8 = 0; k8 < 8; k8++) {
                const float v00 = __shfl_sync(0xffffffffu, accS[k8][0], L1);
                const float v01 = __shfl_sync(0xffffffffu, accS[k8][1], L1);
                const float v02 = __shfl_sync(0xffffffffu, accS[k8][2], L1);
                const float v03 = __shfl_sync(0xffffffffu, accS[k8][3], L1);
                const float v10 = __shfl_sync(0xffffffffu, accS[k8][0], L1 + 2);
                const float v11 = __shfl_sync(0xffffffffu, accS[k8][1], L1 + 2);
                const float v12 = __shfl_sync(0xffffffffu, accS[k8][2], L1 + 2);
                const float v13 = __shfl_sync(0xffffffffu, accS[k8][3], L1 + 2);
                unsigned a[4];
                a[0] = __float_as_uint(odd ? v01 : v00);
                a[1] = __float_as_uint(odd ? v03 : v02);
                a[2] = __float_as_uint(odd ? v11 : v10);
                a[3] = __float_as_uint(odd ? v13 : v12);
#pragma unroll
                for (int nt = 0; nt < 8; nt++) {
                    unsigned bfr[2];
                    const float* bp = Vt + (k8*8 + lc)*VST + nt*8 + lg;
                    bfr[0] = to_tf32(bp[0]);
                    bfr[1] = to_tf32(bp[4*VST]);
                    mma_tf32(accO[nt], a, bfr);
                }
            }
        }
    }

    // ---- epilogue ----
    const float inv0 = 1.f / l0, inv1 = 1.f / l1;
    const int r0g = q0 + wm + lg, r1g = r0g + 8;
#pragma unroll
    for (int nt = 0; nt < 8; nt++) {
        const int col = nt*8 + 2*lc;
        *(float2*)(Ob + (size_t)r0g * D_MODEL + col) =
            make_float2(accO[nt][0]*inv0, accO[nt][1]*inv0);
        *(float2*)(Ob + (size_t)r1g * D_MODEL + col) =
            make_float2(accO[nt][2]*inv1, accO[nt][3]*inv1);
    }
}

// ===========================================================================
extern "C" void kernel_launch(void* const* d_in, const int* in_sizes, int n_in,
                              void* d_out, int out_size)
{
    const float* X  = (const float*)d_in[0];
    const float* Wq = (const float*)d_in[1];
    const float* bq = (const float*)d_in[2];
    const float* Wk = (const float*)d_in[3];
    const float* bk = (const float*)d_in[4];
    const float* Wv = (const float*)d_in[5];
    const float* bv = (const float*)d_in[6];
    const float* Wo = (const float*)d_in[7];
    const float* bo = (const float*)d_in[8];
    float* out = (float*)d_out;

    float *qp, *kp, *vp, *ap;
    cudaGetSymbolAddress((void**)&qp, g_Q);
    cudaGetSymbolAddress((void**)&kp, g_K);
    cudaGetSymbolAddress((void**)&vp, g_V);
    cudaGetSymbolAddress((void**)&ap, g_A);

    cudaFuncSetAttribute(gemm_cpa, cudaFuncAttributeMaxDynamicSharedMemorySize, GEMM_SMEM);
    cudaFuncSetAttribute(flash4,   cudaFuncAttributeMaxDynamicSharedMemorySize, FLASH_SMEM);

    rope_table<<<SEQ*512/256, 256>>>();

    dim3 gblk(D_MODEL / GBN, MTOT / GBM);   // (8, 64)
    gemm_cpa<<<gblk, 256, GEMM_SMEM>>>(X, Wq, bq, qp, 1);
    gemm_cpa<<<gblk, 256, GEMM_SMEM>>>(X, Wk, bk, kp, 1);
    gemm_cpa<<<gblk, 256, GEMM_SMEM>>>(X, Wv, bv, vp, 0);

    flash4<<<dim3(SEQ / FBM, NHEADS, BATCH), 256, FLASH_SMEM>>>(qp, kp, vp, ap);

    gemm_cpa<<<gblk, 256, GEMM_SMEM>>>(ap, Wo, bo, out, 0);
}

// round 7
// speedup vs baseline: 1.2576x; 1.2576x over previous
#include <cuda_runtime.h>
#include <cuda_fp16.h>
#include <math.h>
#include <stdint.h>

#define D_MODEL 1024
#define SEQ     2048
#define NHEADS  16
#define HDIM    64
#define BATCH   4
#define MTOT    (BATCH*SEQ)

// Scratch (allocation-free rule: __device__ globals)
__device__ __half g_X16[(size_t)MTOT * D_MODEL];
__device__ __half g_Q[(size_t)MTOT * D_MODEL];
__device__ __half g_K[(size_t)MTOT * D_MODEL];
__device__ __half g_V[(size_t)MTOT * D_MODEL];
__device__ __half g_A16[(size_t)MTOT * D_MODEL];
__device__ float2 g_RT[(size_t)SEQ * 512];   // RoPE cos/sin table

// ---------------------------------------------------------------------------
// helpers
// ---------------------------------------------------------------------------
__device__ __forceinline__ void mma_f16(float* d, const unsigned* a, const unsigned* b) {
    asm volatile(
        "mma.sync.aligned.m16n8k16.row.col.f32.f16.f16.f32 "
        "{%0,%1,%2,%3}, {%4,%5,%6,%7}, {%8,%9}, {%0,%1,%2,%3};\n"
        : "+f"(d[0]), "+f"(d[1]), "+f"(d[2]), "+f"(d[3])
        : "r"(a[0]), "r"(a[1]), "r"(a[2]), "r"(a[3]), "r"(b[0]), "r"(b[1]));
}
__device__ __forceinline__ unsigned pack_h2(float lo, float hi) {
    unsigned r; asm("cvt.rn.f16x2.f32 %0, %1, %2;" : "=r"(r) : "f"(hi), "f"(lo));
    return r;
}
__device__ __forceinline__ void ldsm4t(unsigned* r, uint32_t addr) {
    asm volatile("ldmatrix.sync.aligned.m8n8.x4.trans.shared.b16 {%0,%1,%2,%3}, [%4];"
                 : "=r"(r[0]), "=r"(r[1]), "=r"(r[2]), "=r"(r[3]) : "r"(addr));
}
__device__ __forceinline__ uint32_t smem_u32(const void* p) {
    uint32_t a;
    asm("{ .reg .u64 t; cvta.to.shared.u64 t, %1; cvt.u32.u64 %0, t; }" : "=r"(a) : "l"(p));
    return a;
}
__device__ __forceinline__ void cpa16(uint32_t dst, const void* src) {
    asm volatile("cp.async.cg.shared.global [%0], [%1], 16;" :: "r"(dst), "l"(src));
}
#define CPA_COMMIT() asm volatile("cp.async.commit_group;" ::: "memory")
#define CPA_WAIT(n)  asm volatile("cp.async.wait_group %0;" :: "n"(n) : "memory")

// exp2 on the FMA pipe (no MUFU). Valid for x <= ~0; clamps at -125.
__device__ __forceinline__ float fexp2(float x) {
    x = fmaxf(x, -125.f);
    float t = x + 12582912.f;
    int  ix = __float_as_int(t) - 0x4B400000;
    float f = x - (t - 12582912.f);
    float p = 1.3333558146e-3f;
    p = fmaf(p, f, 9.6181291076e-3f);
    p = fmaf(p, f, 5.5504108665e-2f);
    p = fmaf(p, f, 2.4022650696e-1f);
    p = fmaf(p, f, 6.9314718056e-1f);
    p = fmaf(p, f, 1.0f);
    return p * __int_as_float((ix + 127) << 23);
}

// ===========================================================================
// X -> fp16 (once per launch)
// ===========================================================================
__global__ __launch_bounds__(256) void cvtX(const float4* __restrict__ X4,
                                            __half* __restrict__ O) {
    const size_t i = (size_t)blockIdx.x * 256 + threadIdx.x;  // each: 8 floats
    float4 a = X4[2*i], b = X4[2*i + 1];
    uint4 o;
    o.x = pack_h2(a.x, a.y); o.y = pack_h2(a.z, a.w);
    o.z = pack_h2(b.x, b.y); o.w = pack_h2(b.z, b.w);
    *(uint4*)(O + 8*i) = o;
}

// ===========================================================================
// RoPE table
// ===========================================================================
__global__ __launch_bounds__(256) void rope_table() {
    const int i = blockIdx.x * 256 + threadIdx.x;
    const int pos = i >> 9, p = i & 511;
    const float NEG_L2B = -0.02595256324130752f;
    const float fr = exp2f((float)p * NEG_L2B);
    float s, c; sincosf((float)pos * fr, &s, &c);
    g_RT[i] = make_float2(c, s);
}

// ===========================================================================
// fp16 GEMM (m16n8k16): C = A16 @ W + bias, opt RoPE, out fp32 or fp16.
// CTA 128x128, BK=32, 8 warps (2m x 4n), warp 64x32, mt=4 nt=4 ks=2.
// A via cp.async (fp16 GMEM); W fp32 -> half2-packed [n][k] smem via regs.
// ===========================================================================
#define GBM 128
#define GBN 128
#define GBK 32
#define ASTB 80                       // bytes/row: 32 halves + 8 pad
#define BSTB 80
#define ASZB (128*ASTB)               // 10240 B / stage
#define BSZB (128*BSTB)
#define GEMM_SMEM (2*(ASZB+BSZB))     // 40960 B
#define NCH (D_MODEL/GBK)             // 32

__global__ __launch_bounds__(256, 2) void gemm_f16(
    const __half* __restrict__ A16, const float* __restrict__ W,
    const float* __restrict__ bias, float* __restrict__ Cf,
    __half* __restrict__ Ch, int outHalf, int applyRope)
{
    extern __shared__ char smc[];
    char* As = smc;
    char* Bs = smc + 2*ASZB;
    const uint32_t s_a = smem_u32(As);

    const int t = threadIdx.x, lane = t & 31, wid = t >> 5;
    const int lg = lane >> 2, lc = lane & 3;
    const int wm = (wid >> 2) * 64, wn = (wid & 3) * 32;
    const int m0 = blockIdx.y * GBM, n0 = blockIdx.x * GBN;

    // A loader: row = t>>1, half-row = t&1 (2 x 16B granules)
    const __half* Asrc = A16 + (size_t)(m0 + (t >> 1)) * D_MODEL + (t & 1) * 16;
    const uint32_t a_dst = s_a + (uint32_t)((t >> 1) * ASTB + (t & 1) * 32);

#define GA_LOAD(cc, buf) do { \
    const __half* sp_ = Asrc + (size_t)(cc) * GBK; \
    cpa16(a_dst + (buf)*ASZB,      sp_); \
    cpa16(a_dst + (buf)*ASZB + 16, sp_ + 8); \
} while (0)

    // B loader: kp = t&15 (k-pair), nb = (t>>4)*8 (8 n-values)
    const int kp = t & 15, nb = (t >> 4) * 8;
    const float* Wsrc = W + n0 + nb;
    float4 pb0, pb1, pb2, pb3;

#define GB_LDG(cc) do { \
    const float* w0_ = Wsrc + (size_t)((cc)*GBK + 2*kp) * D_MODEL; \
    pb0 = *(const float4*)(w0_);            pb1 = *(const float4*)(w0_ + 4); \
    pb2 = *(const float4*)(w0_ + D_MODEL);  pb3 = *(const float4*)(w0_ + D_MODEL + 4); \
} while (0)

#define GB_STS(buf) do { \
    char* bb_ = Bs + (buf)*BSZB; \
    const float* f0_ = (const float*)&pb0; const float* f1_ = (const float*)&pb1; \
    const float* f2_ = (const float*)&pb2; const float* f3_ = (const float*)&pb3; \
    _Pragma("unroll") \
    for (int j_ = 0; j_ < 4; j_++) { \
        *(unsigned*)(bb_ + (nb + j_)*BSTB + kp*4)     = pack_h2(f0_[j_], f2_[j_]); \
        *(unsigned*)(bb_ + (nb + 4 + j_)*BSTB + kp*4) = pack_h2(f1_[j_], f3_[j_]); \
    } \
} while (0)

    float acc[4][4][4];
#pragma unroll
    for (int i = 0; i < 4; i++)
#pragma unroll
        for (int j = 0; j < 4; j++)
#pragma unroll
            for (int k = 0; k < 4; k++) acc[i][j][k] = 0.f;

    // prologue
    GB_LDG(0); GB_STS(0);
    GA_LOAD(0, 0); CPA_COMMIT();
    GB_LDG(1);

#pragma unroll 1
    for (int c = 0; c < NCH; c++) {
        if (c + 1 < NCH) {
            GB_STS((c + 1) & 1);
            GA_LOAD(c + 1, (c + 1) & 1);
            CPA_COMMIT();
        }
        if (c + 2 < NCH) GB_LDG(c + 2);
        if (c + 1 < NCH) { CPA_WAIT(1); } else { CPA_WAIT(0); }
        __syncthreads();

        const char* Ab = As + (c & 1)*ASZB;
        const char* Bb = Bs + (c & 1)*BSZB;
#pragma unroll
        for (int ks = 0; ks < 2; ks++) {
            unsigned af[4][4], bf[4][2];
#pragma unroll
            for (int mt = 0; mt < 4; mt++) {
                const char* ap = Ab + (wm + mt*16 + lg)*ASTB + ks*32 + lc*4;
                af[mt][0] = *(const unsigned*)(ap);
                af[mt][1] = *(const unsigned*)(ap + 8*ASTB);
                af[mt][2] = *(const unsigned*)(ap + 16);
                af[mt][3] = *(const unsigned*)(ap + 8*ASTB + 16);
            }
#pragma unroll
            for (int nt = 0; nt < 4; nt++) {
                const char* bp = Bb + (wn + nt*8 + lg)*BSTB + ks*32 + lc*4;
                bf[nt][0] = *(const unsigned*)(bp);
                bf[nt][1] = *(const unsigned*)(bp + 16);
            }
#pragma unroll
            for (int mt = 0; mt < 4; mt++)
#pragma unroll
                for (int nt = 0; nt < 4; nt++)
                    mma_f16(acc[mt][nt], af[mt], bf[nt]);
        }
        __syncthreads();
    }

    // Epilogue: bias (+RoPE), store fp32 or fp16.
#pragma unroll
    for (int nt = 0; nt < 4; nt++) {
        const int col = n0 + wn + nt*8 + 2*lc;
        const float b0 = bias[col], b1 = bias[col + 1];
        const float2* rt = &g_RT[(size_t)(col >> 1)];
#pragma unroll
        for (int mt = 0; mt < 4; mt++) {
#pragma unroll
            for (int hh = 0; hh < 2; hh++) {
                const int row = m0 + wm + mt*16 + lg + 8*hh;
                float v0 = acc[mt][nt][2*hh + 0] + b0;
                float v1 = acc[mt][nt][2*hh + 1] + b1;
                if (applyRope) {
                    const float2 cs = rt[(size_t)(row & (SEQ-1)) * 512];
                    const float r0 = v0 * cs.x - v1 * cs.y;
                    v1 = v0 * cs.y + v1 * cs.x;
                    v0 = r0;
                }
                if (outHalf)
                    *(unsigned*)(Ch + (size_t)row * D_MODEL + col) = pack_h2(v0, v1);
                else
                    *(float2*)(Cf + (size_t)row * D_MODEL + col) = make_float2(v0, v1);
            }
        }
    }
}

// ===========================================================================
// Flash attention fp16 (m16n8k16): BM=128, BN=64, 8 warps (m16 stripes).
// K as [kv][hd] = B-fragment layout; V via ldmatrix.x4.trans; P repacked
// in registers. All tiles via cp.async, K/V double buffered.
// ===========================================================================
#define FQSTB 144                 // 64 halves + 8 pad
#define FQSZB (128*FQSTB)         // 18432
#define FKSZB (64*FQSTB)          // 9216 per buffer
#define FLASH_SMEM (FQSZB + 4*FKSZB)   // 55296

__global__ __launch_bounds__(256, 2) void flash_f16(
    const __half* __restrict__ Q, const __half* __restrict__ K,
    const __half* __restrict__ V, __half* __restrict__ O)
{
    extern __shared__ char smc[];
    char* Qs = smc;
    char* Ks = smc + FQSZB;
    char* Vs = Ks + 2*FKSZB;
    const uint32_t s_q = smem_u32(Qs);
    const uint32_t s_k = smem_u32(Ks);
    const uint32_t s_v = smem_u32(Vs);

    const int t = threadIdx.x, lane = t & 31, w = t >> 5;
    const int lg = lane >> 2, lc = lane & 3;
    const int wm = w * 16;
    const int qt = blockIdx.x, h = blockIdx.y, b = blockIdx.z;
    const int q0 = qt * 128;

    const __half* Qb = Q + (size_t)b * SEQ * D_MODEL + (size_t)h * HDIM;
    const __half* Kb = K + (size_t)b * SEQ * D_MODEL + (size_t)h * HDIM;
    const __half* Vb = V + (size_t)b * SEQ * D_MODEL + (size_t)h * HDIM;
    __half*       Ob = O + (size_t)b * SEQ * D_MODEL + (size_t)h * HDIM;

#define FKV_LOAD(kt_, buf) do { \
    const int r_ = t >> 2; \
    const int k0_ = (kt_) * 64; \
    const __half* kr_ = Kb + (size_t)(k0_ + r_) * D_MODEL; \
    const __half* vr_ = Vb + (size_t)(k0_ + r_) * D_MODEL; \
    _Pragma("unroll") \
    for (int i_ = 0; i_ < 2; i_++) { \
        const int gr_ = (t & 3)*2 + i_; \
        cpa16(s_k + (buf)*FKSZB + (uint32_t)(r_*FQSTB + gr_*16), kr_ + gr_*8); \
        cpa16(s_v + (buf)*FKSZB + (uint32_t)(r_*FQSTB + gr_*16), vr_ + gr_*8); \
    } \
} while (0)

    // prologue: Q + KV tile 0
    {
        const int r = t >> 1;
        const __half* qr = Qb + (size_t)(q0 + r) * D_MODEL;
#pragma unroll
        for (int i = 0; i < 4; i++) {
            const int gr = (t & 1)*4 + i;
            cpa16(s_q + (uint32_t)(r*FQSTB + gr*16), qr + gr*8);
        }
    }
    FKV_LOAD(0, 0);
    CPA_COMMIT();

    float accO[8][4];
#pragma unroll
    for (int i = 0; i < 8; i++)
#pragma unroll
        for (int j = 0; j < 4; j++) accO[i][j] = 0.f;
    float m0 = -1e30f, m1 = -1e30f, l0 = 0.f, l1 = 0.f;

    const float QSC = 0.125f * 1.4426950408889634f;
    const int ntiles = 2*qt + 2;

#pragma unroll 1
    for (int kt = 0; kt < ntiles; kt++) {
        const int k0 = kt * 64;
        const int buf = kt & 1;
        CPA_WAIT(0);
        __syncthreads();
        if (kt + 1 < ntiles) FKV_LOAD(kt + 1, buf ^ 1);
        CPA_COMMIT();

        if (k0 <= q0 + wm + 15) {
            const char* Kbuf = Ks + buf*FKSZB;

            // ---- S = Q K^T ----
            float accS[8][4];
#pragma unroll
            for (int i = 0; i < 8; i++)
#pragma unroll
                for (int j = 0; j < 4; j++) accS[i][j] = 0.f;
#pragma unroll
            for (int ks = 0; ks < 4; ks++) {
                unsigned a[4];
                const char* ap = Qs + (wm + lg)*FQSTB + ks*32 + lc*4;
                a[0] = *(const unsigned*)(ap);
                a[1] = *(const unsigned*)(ap + 8*FQSTB);
                a[2] = *(const unsigned*)(ap + 16);
                a[3] = *(const unsigned*)(ap + 8*FQSTB + 16);
#pragma unroll
                for (int nt = 0; nt < 8; nt++) {
                    unsigned bfr[2];
                    const char* bp = Kbuf + (nt*8 + lg)*FQSTB + ks*32 + lc*4;
                    bfr[0] = *(const unsigned*)(bp);
                    bfr[1] = *(const unsigned*)(bp + 16);
                    mma_f16(accS[nt], a, bfr);
                }
            }

            // base-2 scale
#pragma unroll
            for (int nt = 0; nt < 8; nt++) {
                accS[nt][0] *= QSC; accS[nt][1] *= QSC;
                accS[nt][2] *= QSC; accS[nt][3] *= QSC;
            }

            // causal mask on diagonal tiles
            if (k0 + 63 > q0 + wm) {
                const int r0g = q0 + wm + lg, r1g = r0g + 8;
#pragma unroll
                for (int nt = 0; nt < 8; nt++) {
                    const int c = k0 + nt*8 + 2*lc;
                    if (c     > r0g) accS[nt][0] = -1e30f;
                    if (c + 1 > r0g) accS[nt][1] = -1e30f;
                    if (c     > r1g) accS[nt][2] = -1e30f;
                    if (c + 1 > r1g) accS[nt][3] = -1e30f;
                }
            }

            // ---- online softmax ----
            float mx0 = -1e30f, mx1 = -1e30f;
#pragma unroll
            for (int nt = 0; nt < 8; nt++) {
                mx0 = fmaxf(mx0, fmaxf(accS[nt][0], accS[nt][1]));
                mx1 = fmaxf(mx1, fmaxf(accS[nt][2], accS[nt][3]));
            }
            mx0 = fmaxf(mx0, __shfl_xor_sync(0xffffffffu, mx0, 1));
            mx0 = fmaxf(mx0, __shfl_xor_sync(0xffffffffu, mx0, 2));
            mx1 = fmaxf(mx1, __shfl_xor_sync(0xffffffffu, mx1, 1));
            mx1 = fmaxf(mx1, __shfl_xor_sync(0xffffffffu, mx1, 2));
            const float mn0 = fmaxf(m0, mx0), mn1 = fmaxf(m1, mx1);
            const float al0 = fexp2(m0 - mn0), al1 = fexp2(m1 - mn1);
            float s0 = 0.f, s1 = 0.f;
#pragma unroll
            for (int nt = 0; nt < 8; nt++) {
                accS[nt][0] = fexp2(accS[nt][0] - mn0);
                accS[nt][1] = fexp2(accS[nt][1] - mn0);
                accS[nt][2] = fexp2(accS[nt][2] - mn1);
                accS[nt][3] = fexp2(accS[nt][3] - mn1);
                s0 += accS[nt][0] + accS[nt][1];
                s1 += accS[nt][2] + accS[nt][3];
            }
            s0 += __shfl_xor_sync(0xffffffffu, s0, 1);
            s0 += __shfl_xor_sync(0xffffffffu, s0, 2);
            s1 += __shfl_xor_sync(0xffffffffu, s1, 1);
            s1 += __shfl_xor_sync(0xffffffffu, s1, 2);
            l0 = l0*al0 + s0;  l1 = l1*al1 + s1;
            m0 = mn0;          m1 = mn1;
#pragma unroll
            for (int nt = 0; nt < 8; nt++) {
                accO[nt][0] *= al0; accO[nt][1] *= al0;
                accO[nt][2] *= al1; accO[nt][3] *= al1;
            }

            // ---- O += P V : P repack in registers, V via ldmatrix.trans ----
            const uint32_t vb = s_v + buf*FKSZB;
            const int g = lane >> 3, li = lane & 7;
#pragma unroll
            for (int ks2 = 0; ks2 < 4; ks2++) {
                unsigned aP[4];
                aP[0] = pack_h2(accS[2*ks2][0],     accS[2*ks2][1]);
                aP[1] = pack_h2(accS[2*ks2][2],     accS[2*ks2][3]);
                aP[2] = pack_h2(accS[2*ks2 + 1][0], accS[2*ks2 + 1][1]);
                aP[3] = pack_h2(accS[2*ks2 + 1][2], accS[2*ks2 + 1][3]);
#pragma unroll
                for (int ntp = 0; ntp < 4; ntp++) {
                    unsigned r[4];
                    const uint32_t addr = vb
                        + (uint32_t)((ks2*16 + (g & 1)*8 + li) * FQSTB
                                     + (ntp*16 + (g >> 1)*8) * 2);
                    ldsm4t(r, addr);
                    mma_f16(accO[2*ntp],     aP, r);
                    mma_f16(accO[2*ntp + 1], aP, r + 2);
                }
            }
        }
    }

    // ---- epilogue (fp16 out) ----
    const float inv0 = 1.f / l0, inv1 = 1.f / l1;
    const int r0g = q0 + wm + lg, r1g = r0g + 8;
#pragma unroll
    for (int nt = 0; nt < 8; nt++) {
        const int col = nt*8 + 2*lc;
        *(unsigned*)(Ob + (size_t)r0g * D_MODEL + col) =
            pack_h2(accO[nt][0]*inv0, accO[nt][1]*inv0);
        *(unsigned*)(Ob + (size_t)r1g * D_MODEL + col) =
            pack_h2(accO[nt][2]*inv1, accO[nt][3]*inv1);
    }
}

// ===========================================================================
extern "C" void kernel_launch(void* const* d_in, const int* in_sizes, int n_in,
                              void* d_out, int out_size)
{
    const float* X  = (const float*)d_in[0];
    const float* Wq = (const float*)d_in[1];
    const float* bq = (const float*)d_in[2];
    const float* Wk = (const float*)d_in[3];
    const float* bk = (const float*)d_in[4];
    const float* Wv = (const float*)d_in[5];
    const float* bv = (const float*)d_in[6];
    const float* Wo = (const float*)d_in[7];
    const float* bo = (const float*)d_in[8];
    float* out = (float*)d_out;

    __half *x16, *qp, *kp, *vp, *ap;
    cudaGetSymbolAddress((void**)&x16, g_X16);
    cudaGetSymbolAddress((void**)&qp,  g_Q);
    cudaGetSymbolAddress((void**)&kp,  g_K);
    cudaGetSymbolAddress((void**)&vp,  g_V);
    cudaGetSymbolAddress((void**)&ap,  g_A16);

    cudaFuncSetAttribute(gemm_f16,  cudaFuncAttributeMaxDynamicSharedMemorySize, GEMM_SMEM);
    cudaFuncSetAttribute(flash_f16, cudaFuncAttributeMaxDynamicSharedMemorySize, FLASH_SMEM);

    cvtX<<<(size_t)MTOT * D_MODEL / (256*8), 256>>>((const float4*)X, x16);
    rope_table<<<SEQ*512/256, 256>>>();

    dim3 gblk(D_MODEL / GBN, MTOT / GBM);   // (8, 64)
    gemm_f16<<<gblk, 256, GEMM_SMEM>>>(x16, Wq, bq, nullptr, qp, 1, 1);
    gemm_f16<<<gblk, 256, GEMM_SMEM>>>(x16, Wk, bk, nullptr, kp, 1, 1);
    gemm_f16<<<gblk, 256, GEMM_SMEM>>>(x16, Wv, bv, nullptr, vp, 1, 0);

    flash_f16<<<dim3(SEQ / 128, NHEADS, BATCH), 256, FLASH_SMEM>>>(qp, kp, vp, ap);

    gemm_f16<<<gblk, 256, GEMM_SMEM>>>(ap, Wo, bo, out, nullptr, 0, 0);
}

// round 8
// speedup vs baseline: 1.9711x; 1.5673x over previous
#include <cuda_runtime.h>
#include <cuda_fp16.h>
#include <math.h>
#include <stdint.h>

#define D_MODEL 1024
#define SEQ     2048
#define NHEADS  16
#define HDIM    64
#define BATCH   4
#define MTOT    (BATCH*SEQ)

// Scratch (allocation-free rule: __device__ globals)
__device__ __half g_X16[(size_t)MTOT * D_MODEL];
__device__ __half g_W16[4][(size_t)D_MODEL * D_MODEL];
__device__ __half g_Q[(size_t)MTOT * D_MODEL];
__device__ __half g_K[(size_t)MTOT * D_MODEL];
__device__ __half g_V[(size_t)MTOT * D_MODEL];
__device__ __half g_A16[(size_t)MTOT * D_MODEL];
__device__ float2 g_RT[(size_t)SEQ * 512];   // RoPE cos/sin table

// ---------------------------------------------------------------------------
// helpers
// ---------------------------------------------------------------------------
__device__ __forceinline__ void mma_f16(float* d, const unsigned* a, const unsigned* b) {
    asm volatile(
        "mma.sync.aligned.m16n8k16.row.col.f32.f16.f16.f32 "
        "{%0,%1,%2,%3}, {%4,%5,%6,%7}, {%8,%9}, {%0,%1,%2,%3};\n"
        : "+f"(d[0]), "+f"(d[1]), "+f"(d[2]), "+f"(d[3])
        : "r"(a[0]), "r"(a[1]), "r"(a[2]), "r"(a[3]), "r"(b[0]), "r"(b[1]));
}
__device__ __forceinline__ unsigned pack_h2(float lo, float hi) {
    unsigned r; asm("cvt.rn.f16x2.f32 %0, %1, %2;" : "=r"(r) : "f"(hi), "f"(lo));
    return r;
}
__device__ __forceinline__ void ldsm4(unsigned* r, uint32_t addr) {
    asm volatile("ldmatrix.sync.aligned.m8n8.x4.shared.b16 {%0,%1,%2,%3}, [%4];"
                 : "=r"(r[0]), "=r"(r[1]), "=r"(r[2]), "=r"(r[3]) : "r"(addr));
}
__device__ __forceinline__ void ldsm4t(unsigned* r, uint32_t addr) {
    asm volatile("ldmatrix.sync.aligned.m8n8.x4.trans.shared.b16 {%0,%1,%2,%3}, [%4];"
                 : "=r"(r[0]), "=r"(r[1]), "=r"(r[2]), "=r"(r[3]) : "r"(addr));
}
__device__ __forceinline__ uint32_t smem_u32(const void* p) {
    uint32_t a;
    asm("{ .reg .u64 t; cvta.to.shared.u64 t, %1; cvt.u32.u64 %0, t; }" : "=r"(a) : "l"(p));
    return a;
}
__device__ __forceinline__ void cpa16(uint32_t dst, const void* src) {
    asm volatile("cp.async.cg.shared.global [%0], [%1], 16;" :: "r"(dst), "l"(src));
}
#define CPA_COMMIT() asm volatile("cp.async.commit_group;" ::: "memory")
#define CPA_WAIT(n)  asm volatile("cp.async.wait_group %0;" :: "n"(n) : "memory")

// exp2 on the FMA pipe (no MUFU). Valid for x <= ~0; clamps at -125.
__device__ __forceinline__ float fexp2(float x) {
    x = fmaxf(x, -125.f);
    float t = x + 12582912.f;
    int  ix = __float_as_int(t) - 0x4B400000;
    float f = x - (t - 12582912.f);
    float p = 1.3333558146e-3f;
    p = fmaf(p, f, 9.6181291076e-3f);
    p = fmaf(p, f, 5.5504108665e-2f);
    p = fmaf(p, f, 2.4022650696e-1f);
    p = fmaf(p, f, 6.9314718056e-1f);
    p = fmaf(p, f, 1.0f);
    return p * __int_as_float((ix + 127) << 23);
}

// ===========================================================================
// fp32 -> fp16 bulk convert (8 floats / thread)
// ===========================================================================
__global__ __launch_bounds__(256) void cvtX(const float4* __restrict__ X4,
                                            __half* __restrict__ O) {
    const size_t i = (size_t)blockIdx.x * 256 + threadIdx.x;
    float4 a = X4[2*i], b = X4[2*i + 1];
    uint4 o;
    o.x = pack_h2(a.x, a.y); o.y = pack_h2(a.z, a.w);
    o.z = pack_h2(b.x, b.y); o.w = pack_h2(b.z, b.w);
    *(uint4*)(O + 8*i) = o;
}

// ===========================================================================
// RoPE table
// ===========================================================================
__global__ __launch_bounds__(256) void rope_table() {
    const int i = blockIdx.x * 256 + threadIdx.x;
    const int pos = i >> 9, p = i & 511;
    const float NEG_L2B = -0.02595256324130752f;
    const float fr = exp2f((float)p * NEG_L2B);
    float s, c; sincosf((float)pos * fr, &s, &c);
    g_RT[i] = make_float2(c, s);
}

// ===========================================================================
// fp16 GEMM (m16n8k16): C = A16 @ W16 + bias, opt RoPE, out fp32 or fp16.
// CTA 128x128, BK=32, 3-stage cp.async, fragments via ldmatrix.
// 8 warps (2m x 4n), warp 64x32 per ks, mt=4 nt=4 ks=2.
// A smem [128m][32k] pad->80B rows; B smem [32k][128n] pad->272B rows.
// ===========================================================================
#define G_AST 80
#define G_BST 272
#define G_ASZ (128*G_AST)            // 10240 B
#define G_BSZ (32*G_BST)             // 8704 B
#define G_STG (G_ASZ + G_BSZ)        // 18944 B / stage
#define GEMM_SMEM (3*G_STG)          // 56832 B
#define NCH (D_MODEL/32)             // 32

__global__ __launch_bounds__(256, 2) void gemm_f16(
    const __half* __restrict__ A16, const __half* __restrict__ W16,
    const float* __restrict__ bias, float* __restrict__ Cf,
    __half* __restrict__ Ch, int outHalf, int applyRope)
{
    extern __shared__ char smc[];
    const uint32_t s0 = smem_u32(smc);

    const int t = threadIdx.x, lane = t & 31, wid = t >> 5;
    const int lg = lane >> 2, lc = lane & 3;
    const int wm = (wid >> 2) * 64, wn = (wid & 3) * 32;
    const int m0 = blockIdx.y * 128, n0 = blockIdx.x * 128;

    // A loader: 2 threads/row, 32B each
    const __half* Asrc = A16 + (size_t)(m0 + (t >> 1)) * D_MODEL + (t & 1) * 16;
    const uint32_t a_dst = s0 + (uint32_t)((t >> 1) * G_AST + (t & 1) * 32);
    // B loader: kr = t>>3, two 16B segs (t&7), (t&7)+8  (contiguous 128B / 8 lanes)
    const int b_kr = t >> 3, b_sg = t & 7;
    const __half* Bsrc = W16 + (size_t)b_kr * D_MODEL + n0 + b_sg * 8;
    const uint32_t b_dst = s0 + (uint32_t)(G_ASZ + b_kr * G_BST + b_sg * 16);

#define G_LOAD(cc, stg) do { \
    const uint32_t so_ = (stg) * G_STG; \
    const __half* as_ = Asrc + (size_t)(cc) * 32; \
    cpa16(a_dst + so_,      as_); \
    cpa16(a_dst + so_ + 16, as_ + 8); \
    const __half* bs_ = Bsrc + (size_t)(cc) * 32 * D_MODEL; \
    cpa16(b_dst + so_,       bs_); \
    cpa16(b_dst + so_ + 128, bs_ + 64); \
} while (0)

    // fragment address bases (constant over loop)
    const int g = lane >> 3, li = lane & 7;
    const uint32_t a_frag = s0 + (uint32_t)((wm + ((lane >> 3) & 1) * 8 + li) * G_AST
                                            + (lane >> 4) * 16);
    const uint32_t b_frag = s0 + (uint32_t)(G_ASZ + ((g & 1) * 8 + li) * G_BST
                                            + (wn + (g >> 1) * 8) * 2);

    float acc[4][4][4];
#pragma unroll
    for (int i = 0; i < 4; i++)
#pragma unroll
        for (int j = 0; j < 4; j++)
#pragma unroll
            for (int k = 0; k < 4; k++) acc[i][j][k] = 0.f;

    G_LOAD(0, 0); CPA_COMMIT();
    G_LOAD(1, 1); CPA_COMMIT();

#pragma unroll 1
    for (int c = 0; c < NCH; c++) {
        CPA_WAIT(1);
        __syncthreads();
        if (c + 2 < NCH) G_LOAD(c + 2, (c + 2) % 3);
        CPA_COMMIT();                      // unconditional: keeps group math exact

        const uint32_t so = (uint32_t)((c % 3) * G_STG);
#pragma unroll
        for (int ks = 0; ks < 2; ks++) {
            unsigned af[4][4], bf[2][4];
#pragma unroll
            for (int mt = 0; mt < 4; mt++)
                ldsm4(af[mt], a_frag + so + (uint32_t)(mt * 16 * G_AST + ks * 32));
#pragma unroll
            for (int ntp = 0; ntp < 2; ntp++)
                ldsm4t(bf[ntp], b_frag + so + (uint32_t)(ks * 16 * G_BST + ntp * 32));
#pragma unroll
            for (int mt = 0; mt < 4; mt++)
#pragma unroll
                for (int nt = 0; nt < 4; nt++)
                    mma_f16(acc[mt][nt], af[mt], bf[nt >> 1] + 2 * (nt & 1));
        }
    }

    // Epilogue: bias (+RoPE), store fp32 or fp16.
#pragma unroll
    for (int nt = 0; nt < 4; nt++) {
        const int col = n0 + wn + nt*8 + 2*lc;
        const float b0 = bias[col], b1 = bias[col + 1];
        const float2* rt = &g_RT[(size_t)(col >> 1)];
#pragma unroll
        for (int mt = 0; mt < 4; mt++) {
#pragma unroll
            for (int hh = 0; hh < 2; hh++) {
                const int row = m0 + wm + mt*16 + lg + 8*hh;
                float v0 = acc[mt][nt][2*hh + 0] + b0;
                float v1 = acc[mt][nt][2*hh + 1] + b1;
                if (applyRope) {
                    const float2 cs = rt[(size_t)(row & (SEQ-1)) * 512];
                    const float r0 = v0 * cs.x - v1 * cs.y;
                    v1 = v0 * cs.y + v1 * cs.x;
                    v0 = r0;
                }
                if (outHalf)
                    *(unsigned*)(Ch + (size_t)row * D_MODEL + col) = pack_h2(v0, v1);
                else
                    *(float2*)(Cf + (size_t)row * D_MODEL + col) = make_float2(v0, v1);
            }
        }
    }
}

// ===========================================================================
// Flash attention fp16 (m16n8k16): unchanged from R7.
// ===========================================================================
#define FQSTB 144
#define FQSZB (128*FQSTB)
#define FKSZB (64*FQSTB)
#define FLASH_SMEM (FQSZB + 4*FKSZB)   // 55296

__global__ __launch_bounds__(256, 2) void flash_f16(
    const __half* __restrict__ Q, const __half* __restrict__ K,
    const __half* __restrict__ V, __half* __restrict__ O)
{
    extern __shared__ char smc[];
    char* Qs = smc;
    char* Ks = smc + FQSZB;
    const uint32_t s_q = smem_u32(Qs);
    const uint32_t s_k = smem_u32(Ks);
    const uint32_t s_v = s_k + 2*FKSZB;

    const int t = threadIdx.x, lane = t & 31, w = t >> 5;
    const int lg = lane >> 2, lc = lane & 3;
    const int wm = w * 16;
    const int qt = blockIdx.x, h = blockIdx.y, b = blockIdx.z;
    const int q0 = qt * 128;

    const __half* Qb = Q + (size_t)b * SEQ * D_MODEL + (size_t)h * HDIM;
    const __half* Kb = K + (size_t)b * SEQ * D_MODEL + (size_t)h * HDIM;
    const __half* Vb = V + (size_t)b * SEQ * D_MODEL + (size_t)h * HDIM;
    __half*       Ob = O + (size_t)b * SEQ * D_MODEL + (size_t)h * HDIM;

#define FKV_LOAD(kt_, buf) do { \
    const int r_ = t >> 2; \
    const int k0_ = (kt_) * 64; \
    const __half* kr_ = Kb + (size_t)(k0_ + r_) * D_MODEL; \
    const __half* vr_ = Vb + (size_t)(k0_ + r_) * D_MODEL; \
    _Pragma("unroll") \
    for (int i_ = 0; i_ < 2; i_++) { \
        const int gr_ = (t & 3)*2 + i_; \
        cpa16(s_k + (buf)*FKSZB + (uint32_t)(r_*FQSTB + gr_*16), kr_ + gr_*8); \
        cpa16(s_v + (buf)*FKSZB + (uint32_t)(r_*FQSTB + gr_*16), vr_ + gr_*8); \
    } \
} while (0)

    {
        const int r = t >> 1;
        const __half* qr = Qb + (size_t)(q0 + r) * D_MODEL;
#pragma unroll
        for (int i = 0; i < 4; i++) {
            const int gr = (t & 1)*4 + i;
            cpa16(s_q + (uint32_t)(r*FQSTB + gr*16), qr + gr*8);
        }
    }
    FKV_LOAD(0, 0);
    CPA_COMMIT();

    float accO[8][4];
#pragma unroll
    for (int i = 0; i < 8; i++)
#pragma unroll
        for (int j = 0; j < 4; j++) accO[i][j] = 0.f;
    float m0 = -1e30f, m1 = -1e30f, l0 = 0.f, l1 = 0.f;

    const float QSC = 0.125f * 1.4426950408889634f;
    const int ntiles = 2*qt + 2;

#pragma unroll 1
    for (int kt = 0; kt < ntiles; kt++) {
        const int k0 = kt * 64;
        const int buf = kt & 1;
        CPA_WAIT(0);
        __syncthreads();
        if (kt + 1 < ntiles) FKV_LOAD(kt + 1, buf ^ 1);
        CPA_COMMIT();

        if (k0 <= q0 + wm + 15) {
            const char* Kbuf = Ks + buf*FKSZB;

            float accS[8][4];
#pragma unroll
            for (int i = 0; i < 8; i++)
#pragma unroll
                for (int j = 0; j < 4; j++) accS[i][j] = 0.f;
#pragma unroll
            for (int ks = 0; ks < 4; ks++) {
                unsigned a[4];
                const char* ap = Qs + (wm + lg)*FQSTB + ks*32 + lc*4;
                a[0] = *(const unsigned*)(ap);
                a[1] = *(const unsigned*)(ap + 8*FQSTB);
                a[2] = *(const unsigned*)(ap + 16);
                a[3] = *(const unsigned*)(ap + 8*FQSTB + 16);
#pragma unroll
                for (int nt = 0; nt < 8; nt++) {
                    unsigned bfr[2];
                    const char* bp = Kbuf + (nt*8 + lg)*FQSTB + ks*32 + lc*4;
                    bfr[0] = *(const unsigned*)(bp);
                    bfr[1] = *(const unsigned*)(bp + 16);
                    mma_f16(accS[nt], a, bfr);
                }
            }

#pragma unroll
            for (int nt = 0; nt < 8; nt++) {
                accS[nt][0] *= QSC; accS[nt][1] *= QSC;
                accS[nt][2] *= QSC; accS[nt][3] *= QSC;
            }

            if (k0 + 63 > q0 + wm) {
                const int r0g = q0 + wm + lg, r1g = r0g + 8;
#pragma unroll
                for (int nt = 0; nt < 8; nt++) {
                    const int c = k0 + nt*8 + 2*lc;
                    if (c     > r0g) accS[nt][0] = -1e30f;
                    if (c + 1 > r0g) accS[nt][1] = -1e30f;
                    if (c     > r1g) accS[nt][2] = -1e30f;
                    if (c + 1 > r1g) accS[nt][3] = -1e30f;
                }
            }

            float mx0 = -1e30f, mx1 = -1e30f;
#pragma unroll
            for (int nt = 0; nt < 8; nt++) {
                mx0 = fmaxf(mx0, fmaxf(accS[nt][0], accS[nt][1]));
                mx1 = fmaxf(mx1, fmaxf(accS[nt][2], accS[nt][3]));
            }
            mx0 = fmaxf(mx0, __shfl_xor_sync(0xffffffffu, mx0, 1));
            mx0 = fmaxf(mx0, __shfl_xor_sync(0xffffffffu, mx0, 2));
            mx1 = fmaxf(mx1, __shfl_xor_sync(0xffffffffu, mx1, 1));
            mx1 = fmaxf(mx1, __shfl_xor_sync(0xffffffffu, mx1, 2));
            const float mn0 = fmaxf(m0, mx0), mn1 = fmaxf(m1, mx1);
            const float al0 = fexp2(m0 - mn0), al1 = fexp2(m1 - mn1);
            float s0 = 0.f, s1 = 0.f;
#pragma unroll
            for (int nt = 0; nt < 8; nt++) {
                accS[nt][0] = fexp2(accS[nt][0] - mn0);
                accS[nt][1] = fexp2(accS[nt][1] - mn0);
                accS[nt][2] = fexp2(accS[nt][2] - mn1);
                accS[nt][3] = fexp2(accS[nt][3] - mn1);
                s0 += accS[nt][0] + accS[nt][1];
                s1 += accS[nt][2] + accS[nt][3];
            }
            s0 += __shfl_xor_sync(0xffffffffu, s0, 1);
            s0 += __shfl_xor_sync(0xffffffffu, s0, 2);
            s1 += __shfl_xor_sync(0xffffffffu, s1, 1);
            s1 += __shfl_xor_sync(0xffffffffu, s1, 2);
            l0 = l0*al0 + s0;  l1 = l1*al1 + s1;
            m0 = mn0;          m1 = mn1;
#pragma unroll
            for (int nt = 0; nt < 8; nt++) {
                accO[nt][0] *= al0; accO[nt][1] *= al0;
                accO[nt][2] *= al1; accO[nt][3] *= al1;
            }

            const uint32_t vb = s_v + buf*FKSZB;
            const int g = lane >> 3, li = lane & 7;
#pragma unroll
            for (int ks2 = 0; ks2 < 4; ks2++) {
                unsigned aP[4];
                aP[0] = pack_h2(accS[2*ks2][0],     accS[2*ks2][1]);
                aP[1] = pack_h2(accS[2*ks2][2],     accS[2*ks2][3]);
                aP[2] = pack_h2(accS[2*ks2 + 1][0], accS[2*ks2 + 1][1]);
                aP[3] = pack_h2(accS[2*ks2 + 1][2], accS[2*ks2 + 1][3]);
#pragma unroll
                for (int ntp = 0; ntp < 4; ntp++) {
                    unsigned r[4];
                    const uint32_t addr = vb
                        + (uint32_t)((ks2*16 + (g & 1)*8 + li) * FQSTB
                                     + (ntp*16 + (g >> 1)*8) * 2);
                    ldsm4t(r, addr);
                    mma_f16(accO[2*ntp],     aP, r);
                    mma_f16(accO[2*ntp + 1], aP, r + 2);
                }
            }
        }
    }

    const float inv0 = 1.f / l0, inv1 = 1.f / l1;
    const int r0g = q0 + wm + lg, r1g = r0g + 8;
#pragma unroll
    for (int nt = 0; nt < 8; nt++) {
        const int col = nt*8 + 2*lc;
        *(unsigned*)(Ob + (size_t)r0g * D_MODEL + col) =
            pack_h2(accO[nt][0]*inv0, accO[nt][1]*inv0);
        *(unsigned*)(Ob + (size_t)r1g * D_MODEL + col) =
            pack_h2(accO[nt][2]*inv1, accO[nt][3]*inv1);
    }
}

// ===========================================================================
extern "C" void kernel_launch(void* const* d_in, const int* in_sizes, int n_in,
                              void* d_out, int out_size)
{
    const float* X  = (const float*)d_in[0];
    const float* Wq = (const float*)d_in[1];
    const float* bq = (const float*)d_in[2];
    const float* Wk = (const float*)d_in[3];
    const float* bk = (const float*)d_in[4];
    const float* Wv = (const float*)d_in[5];
    const float* bv = (const float*)d_in[6];
    const float* Wo = (const float*)d_in[7];
    const float* bo = (const float*)d_in[8];
    float* out = (float*)d_out;

    __half *x16, *w16, *qp, *kp, *vp, *ap;
    cudaGetSymbolAddress((void**)&x16, g_X16);
    cudaGetSymbolAddress((void**)&w16, g_W16);
    cudaGetSymbolAddress((void**)&qp,  g_Q);
    cudaGetSymbolAddress((void**)&kp,  g_K);
    cudaGetSymbolAddress((void**)&vp,  g_V);
    cudaGetSymbolAddress((void**)&ap,  g_A16);
    const size_t WSZ = (size_t)D_MODEL * D_MODEL;

    cudaFuncSetAttribute(gemm_f16,  cudaFuncAttributeMaxDynamicSharedMemorySize, GEMM_SMEM);
    cudaFuncSetAttribute(flash_f16, cudaFuncAttributeMaxDynamicSharedMemorySize, FLASH_SMEM);

    cvtX<<<(size_t)MTOT * D_MODEL / (256*8), 256>>>((const float4*)X, x16);
    cvtX<<<WSZ / (256*8), 256>>>((const float4*)Wq, w16);
    cvtX<<<WSZ / (256*8), 256>>>((const float4*)Wk, w16 + WSZ);
    cvtX<<<WSZ / (256*8), 256>>>((const float4*)Wv, w16 + 2*WSZ);
    cvtX<<<WSZ / (256*8), 256>>>((const float4*)Wo, w16 + 3*WSZ);
    rope_table<<<SEQ*512/256, 256>>>();

    dim3 gblk(D_MODEL / 128, MTOT / 128);   // (8, 64)
    gemm_f16<<<gblk, 256, GEMM_SMEM>>>(x16, w16,         bq, nullptr, qp, 1, 1);
    gemm_f16<<<gblk, 256, GEMM_SMEM>>>(x16, w16 + WSZ,   bk, nullptr, kp, 1, 1);
    gemm_f16<<<gblk, 256, GEMM_SMEM>>>(x16, w16 + 2*WSZ, bv, nullptr, vp, 1, 0);

    flash_f16<<<dim3(SEQ / 128, NHEADS, BATCH), 256, FLASH_SMEM>>>(qp, kp, vp, ap);

    gemm_f16<<<gblk, 256, GEMM_SMEM>>>(ap, w16 + 3*WSZ,  bo, out, nullptr, 0, 0);
}

// round 9
// speedup vs baseline: 2.1010x; 1.0659x over previous
#include <cuda_runtime.h>
#include <cuda_fp16.h>
#include <math.h>
#include <stdint.h>

#define D_MODEL 1024
#define SEQ     2048
#define NHEADS  16
#define HDIM    64
#define BATCH   4
#define MTOT    (BATCH*SEQ)
#define NQKV    3072

// Scratch (allocation-free rule: __device__ globals)
__device__ __half g_X16[(size_t)MTOT * D_MODEL];
__device__ __half g_Wqkv[(size_t)D_MODEL * NQKV];     // [k][3*1024] interleaved
__device__ __half g_Wo16[(size_t)D_MODEL * D_MODEL];
__device__ float  g_Bqkv[NQKV];
__device__ __half g_QKV[(size_t)MTOT * NQKV];         // fused Q|K|V rows
__device__ __half g_A16[(size_t)MTOT * D_MODEL];
__device__ float2 g_RT[(size_t)SEQ * 512];            // RoPE cos/sin table

// ---------------------------------------------------------------------------
// helpers
// ---------------------------------------------------------------------------
__device__ __forceinline__ void mma_f16(float* d, const unsigned* a, const unsigned* b) {
    asm volatile(
        "mma.sync.aligned.m16n8k16.row.col.f32.f16.f16.f32 "
        "{%0,%1,%2,%3}, {%4,%5,%6,%7}, {%8,%9}, {%0,%1,%2,%3};\n"
        : "+f"(d[0]), "+f"(d[1]), "+f"(d[2]), "+f"(d[3])
        : "r"(a[0]), "r"(a[1]), "r"(a[2]), "r"(a[3]), "r"(b[0]), "r"(b[1]));
}
__device__ __forceinline__ unsigned pack_h2(float lo, float hi) {
    unsigned r; asm("cvt.rn.f16x2.f32 %0, %1, %2;" : "=r"(r) : "f"(hi), "f"(lo));
    return r;
}
__device__ __forceinline__ void ldsm4(unsigned* r, uint32_t addr) {
    asm volatile("ldmatrix.sync.aligned.m8n8.x4.shared.b16 {%0,%1,%2,%3}, [%4];"
                 : "=r"(r[0]), "=r"(r[1]), "=r"(r[2]), "=r"(r[3]) : "r"(addr));
}
__device__ __forceinline__ void ldsm4t(unsigned* r, uint32_t addr) {
    asm volatile("ldmatrix.sync.aligned.m8n8.x4.trans.shared.b16 {%0,%1,%2,%3}, [%4];"
                 : "=r"(r[0]), "=r"(r[1]), "=r"(r[2]), "=r"(r[3]) : "r"(addr));
}
__device__ __forceinline__ uint32_t smem_u32(const void* p) {
    uint32_t a;
    asm("{ .reg .u64 t; cvta.to.shared.u64 t, %1; cvt.u32.u64 %0, t; }" : "=r"(a) : "l"(p));
    return a;
}
__device__ __forceinline__ void cpa16(uint32_t dst, const void* src) {
    asm volatile("cp.async.cg.shared.global [%0], [%1], 16;" :: "r"(dst), "l"(src));
}
#define CPA_COMMIT() asm volatile("cp.async.commit_group;" ::: "memory")
#define CPA_WAIT(n)  asm volatile("cp.async.wait_group %0;" :: "n"(n) : "memory")

// exp2 on the FMA pipe (no MUFU). Valid for x <= ~0; clamps at -125.
__device__ __forceinline__ float fexp2(float x) {
    x = fmaxf(x, -125.f);
    float t = x + 12582912.f;
    int  ix = __float_as_int(t) - 0x4B400000;
    float f = x - (t - 12582912.f);
    float p = 1.3333558146e-3f;
    p = fmaf(p, f, 9.6181291076e-3f);
    p = fmaf(p, f, 5.5504108665e-2f);
    p = fmaf(p, f, 2.4022650696e-1f);
    p = fmaf(p, f, 6.9314718056e-1f);
    p = fmaf(p, f, 1.0f);
    return p * __int_as_float((ix + 127) << 23);
}

// ===========================================================================
// converters
// ===========================================================================
__global__ __launch_bounds__(256) void cvtX(const float4* __restrict__ X4,
                                            __half* __restrict__ O) {
    const size_t i = (size_t)blockIdx.x * 256 + threadIdx.x;
    float4 a = X4[2*i], b = X4[2*i + 1];
    uint4 o;
    o.x = pack_h2(a.x, a.y); o.y = pack_h2(a.z, a.w);
    o.z = pack_h2(b.x, b.y); o.w = pack_h2(b.z, b.w);
    *(uint4*)(O + 8*i) = o;
}
// W [k][1024] -> interleaved [k][3072] at column offset matOff
__global__ __launch_bounds__(256) void cvtW(const float4* __restrict__ X4,
                                            __half* __restrict__ O, int matOff) {
    const size_t i = (size_t)blockIdx.x * 256 + threadIdx.x;
    const size_t k = (8*i) >> 10, n = (8*i) & 1023;
    float4 a = X4[2*i], b = X4[2*i + 1];
    uint4 o;
    o.x = pack_h2(a.x, a.y); o.y = pack_h2(a.z, a.w);
    o.z = pack_h2(b.x, b.y); o.w = pack_h2(b.z, b.w);
    *(uint4*)(O + k * NQKV + matOff + n) = o;
}
__global__ __launch_bounds__(256) void fuse_bias(const float* __restrict__ bq,
                                                 const float* __restrict__ bk,
                                                 const float* __restrict__ bv) {
    const int i = blockIdx.x * 256 + threadIdx.x;
    g_Bqkv[i] = (i < 1024) ? bq[i] : (i < 2048 ? bk[i - 1024] : bv[i - 2048]);
}
__global__ __launch_bounds__(256) void rope_table() {
    const int i = blockIdx.x * 256 + threadIdx.x;
    const int pos = i >> 9, p = i & 511;
    const float NEG_L2B = -0.02595256324130752f;
    const float fr = exp2f((float)p * NEG_L2B);
    float s, c; sincosf((float)pos * fr, &s, &c);
    g_RT[i] = make_float2(c, s);
}

// ===========================================================================
// fp16 GEMM (m16n8k16): C = A16 @ W16 + bias, RoPE iff col < ropeLimit.
// CTA 128x128, BK=32, 3-stage cp.async, ldmatrix fragments.
// ===========================================================================
#define G_AST 80
#define G_BST 272
#define G_ASZ (128*G_AST)
#define G_BSZ (32*G_BST)
#define G_STG (G_ASZ + G_BSZ)
#define GEMM_SMEM (3*G_STG)          // 56832 B
#define NCH (D_MODEL/32)             // 32

__global__ __launch_bounds__(256, 2) void gemm_f16(
    const __half* __restrict__ A16, const __half* __restrict__ W16,
    const float* __restrict__ bias, float* __restrict__ Cf,
    __half* __restrict__ Ch, int outHalf, int ropeLimit, int ldb, int ldc)
{
    extern __shared__ char smc[];
    const uint32_t s0 = smem_u32(smc);

    const int t = threadIdx.x, lane = t & 31, wid = t >> 5;
    const int lg = lane >> 2, lc = lane & 3;
    const int wm = (wid >> 2) * 64, wn = (wid & 3) * 32;
    const int m0 = blockIdx.y * 128, n0 = blockIdx.x * 128;

    const __half* Asrc = A16 + (size_t)(m0 + (t >> 1)) * D_MODEL + (t & 1) * 16;
    const uint32_t a_dst = s0 + (uint32_t)((t >> 1) * G_AST + (t & 1) * 32);
    const int b_kr = t >> 3, b_sg = t & 7;
    const __half* Bsrc = W16 + (size_t)b_kr * ldb + n0 + b_sg * 8;
    const uint32_t b_dst = s0 + (uint32_t)(G_ASZ + b_kr * G_BST + b_sg * 16);

#define G_LOAD(cc, stg) do { \
    const uint32_t so_ = (stg) * G_STG; \
    const __half* as_ = Asrc + (size_t)(cc) * 32; \
    cpa16(a_dst + so_,      as_); \
    cpa16(a_dst + so_ + 16, as_ + 8); \
    const __half* bs_ = Bsrc + (size_t)(cc) * 32 * ldb; \
    cpa16(b_dst + so_,       bs_); \
    cpa16(b_dst + so_ + 128, bs_ + 64); \
} while (0)

    const int g = lane >> 3, li = lane & 7;
    const uint32_t a_frag = s0 + (uint32_t)((wm + (lane & 15)) * G_AST + (lane >> 4) * 16);
    const uint32_t b_frag = s0 + (uint32_t)(G_ASZ + ((g & 1) * 8 + li) * G_BST
                                            + (wn + (g >> 1) * 8) * 2);

    float acc[4][4][4];
#pragma unroll
    for (int i = 0; i < 4; i++)
#pragma unroll
        for (int j = 0; j < 4; j++)
#pragma unroll
            for (int k = 0; k < 4; k++) acc[i][j][k] = 0.f;

    G_LOAD(0, 0); CPA_COMMIT();
    G_LOAD(1, 1); CPA_COMMIT();

#pragma unroll 1
    for (int c = 0; c < NCH; c++) {
        CPA_WAIT(1);
        __syncthreads();
        if (c + 2 < NCH) G_LOAD(c + 2, (c + 2) % 3);
        CPA_COMMIT();

        const uint32_t so = (uint32_t)((c % 3) * G_STG);
#pragma unroll
        for (int ks = 0; ks < 2; ks++) {
            unsigned af[4][4], bf[2][4];
#pragma unroll
            for (int mt = 0; mt < 4; mt++)
                ldsm4(af[mt], a_frag + so + (uint32_t)(mt * 16 * G_AST + ks * 32));
#pragma unroll
            for (int ntp = 0; ntp < 2; ntp++)
                ldsm4t(bf[ntp], b_frag + so + (uint32_t)(ks * 16 * G_BST + ntp * 32));
#pragma unroll
            for (int mt = 0; mt < 4; mt++)
#pragma unroll
                for (int nt = 0; nt < 4; nt++)
                    mma_f16(acc[mt][nt], af[mt], bf[nt >> 1] + 2 * (nt & 1));
        }
    }

#pragma unroll
    for (int nt = 0; nt < 4; nt++) {
        const int col = n0 + wn + nt*8 + 2*lc;
        const float b0 = bias[col], b1 = bias[col + 1];
        const bool doRope = col < ropeLimit;
        const float2* rt = &g_RT[(size_t)((col & 1023) >> 1)];
#pragma unroll
        for (int mt = 0; mt < 4; mt++) {
#pragma unroll
            for (int hh = 0; hh < 2; hh++) {
                const int row = m0 + wm + mt*16 + lg + 8*hh;
                float v0 = acc[mt][nt][2*hh + 0] + b0;
                float v1 = acc[mt][nt][2*hh + 1] + b1;
                if (doRope) {
                    const float2 cs = rt[(size_t)(row & (SEQ-1)) * 512];
                    const float r0 = v0 * cs.x - v1 * cs.y;
                    v1 = v0 * cs.y + v1 * cs.x;
                    v0 = r0;
                }
                if (outHalf)
                    *(unsigned*)(Ch + (size_t)row * ldc + col) = pack_h2(v0, v1);
                else
                    *(float2*)(Cf + (size_t)row * ldc + col) = make_float2(v0, v1);
            }
        }
    }
}

// ===========================================================================
// Flash attention fp16: Q/K fragments via ldmatrix; reads fused QKV rows.
// BM=128, BN=64, 8 warps.
// ===========================================================================
#define FQSTB 144
#define FQSZB (128*FQSTB)
#define FKSZB (64*FQSTB)
#define FLASH_SMEM (FQSZB + 4*FKSZB)   // 55296

__global__ __launch_bounds__(256, 2) void flash_f16(
    const __half* __restrict__ QKV, __half* __restrict__ O)
{
    extern __shared__ char smc[];
    const uint32_t s_q = smem_u32(smc);
    const uint32_t s_k = s_q + FQSZB;
    const uint32_t s_v = s_k + 2*FKSZB;

    const int t = threadIdx.x, lane = t & 31, w = t >> 5;
    const int lg = lane >> 2, lc = lane & 3;
    const int wm = w * 16;
    const int qt = blockIdx.x, h = blockIdx.y, b = blockIdx.z;
    const int q0 = qt * 128;

    const __half* Qb = QKV + (size_t)b * SEQ * NQKV + (size_t)h * HDIM;
    const __half* Kb = Qb + 1024;
    const __half* Vb = Qb + 2048;
    __half*       Ob = O + (size_t)b * SEQ * D_MODEL + (size_t)h * HDIM;

#define FKV_LOAD(kt_, buf) do { \
    const int r_ = t >> 2; \
    const int k0_ = (kt_) * 64; \
    const __half* kr_ = Kb + (size_t)(k0_ + r_) * NQKV; \
    const __half* vr_ = Vb + (size_t)(k0_ + r_) * NQKV; \
    _Pragma("unroll") \
    for (int i_ = 0; i_ < 2; i_++) { \
        const int gr_ = (t & 3)*2 + i_; \
        cpa16(s_k + (buf)*FKSZB + (uint32_t)(r_*FQSTB + gr_*16), kr_ + gr_*8); \
        cpa16(s_v + (buf)*FKSZB + (uint32_t)(r_*FQSTB + gr_*16), vr_ + gr_*8); \
    } \
} while (0)

    {
        const int r = t >> 1;
        const __half* qr = Qb + (size_t)(q0 + r) * NQKV;
#pragma unroll
        for (int i = 0; i < 4; i++) {
            const int gr = (t & 1)*4 + i;
            cpa16(s_q + (uint32_t)(r*FQSTB + gr*16), qr + gr*8);
        }
    }
    FKV_LOAD(0, 0);
    CPA_COMMIT();

    float accO[8][4];
#pragma unroll
    for (int i = 0; i < 8; i++)
#pragma unroll
        for (int j = 0; j < 4; j++) accO[i][j] = 0.f;
    float m0 = -1e30f, m1 = -1e30f, l0 = 0.f, l1 = 0.f;

    const float QSC = 0.125f * 1.4426950408889634f;
    const int ntiles = 2*qt + 2;

    // fragment bases
    const uint32_t q_frag = s_q + (uint32_t)((wm + (lane & 15)) * FQSTB + (lane >> 4) * 16);
    const uint32_t k_frag = (uint32_t)((lane & 15) * FQSTB + (lane >> 4) * 16);

#pragma unroll 1
    for (int kt = 0; kt < ntiles; kt++) {
        const int k0 = kt * 64;
        const int buf = kt & 1;
        CPA_WAIT(0);
        __syncthreads();
        if (kt + 1 < ntiles) FKV_LOAD(kt + 1, buf ^ 1);
        CPA_COMMIT();

        if (k0 <= q0 + wm + 15) {
            const uint32_t kb = s_k + buf*FKSZB + k_frag;

            // ---- S = Q K^T (all ldmatrix) ----
            float accS[8][4];
#pragma unroll
            for (int i = 0; i < 8; i++)
#pragma unroll
                for (int j = 0; j < 4; j++) accS[i][j] = 0.f;
#pragma unroll
            for (int ks = 0; ks < 4; ks++) {
                unsigned a[4];
                ldsm4(a, q_frag + ks*32);
#pragma unroll
                for (int ntp = 0; ntp < 4; ntp++) {
                    unsigned kq[4];
                    ldsm4(kq, kb + (uint32_t)(ntp*16*FQSTB + ks*32));
                    unsigned b0[2] = {kq[0], kq[2]};
                    unsigned b1[2] = {kq[1], kq[3]};
                    mma_f16(accS[2*ntp],     a, b0);
                    mma_f16(accS[2*ntp + 1], a, b1);
                }
            }

#pragma unroll
            for (int nt = 0; nt < 8; nt++) {
                accS[nt][0] *= QSC; accS[nt][1] *= QSC;
                accS[nt][2] *= QSC; accS[nt][3] *= QSC;
            }

            if (k0 + 63 > q0 + wm) {
                const int r0g = q0 + wm + lg, r1g = r0g + 8;
#pragma unroll
                for (int nt = 0; nt < 8; nt++) {
                    const int c = k0 + nt*8 + 2*lc;
                    if (c     > r0g) accS[nt][0] = -1e30f;
                    if (c + 1 > r0g) accS[nt][1] = -1e30f;
                    if (c     > r1g) accS[nt][2] = -1e30f;
                    if (c + 1 > r1g) accS[nt][3] = -1e30f;
                }
            }

            float mx0 = -1e30f, mx1 = -1e30f;
#pragma unroll
            for (int nt = 0; nt < 8; nt++) {
                mx0 = fmaxf(mx0, fmaxf(accS[nt][0], accS[nt][1]));
                mx1 = fmaxf(mx1, fmaxf(accS[nt][2], accS[nt][3]));
            }
            mx0 = fmaxf(mx0, __shfl_xor_sync(0xffffffffu, mx0, 1));
            mx0 = fmaxf(mx0, __shfl_xor_sync(0xffffffffu, mx0, 2));
            mx1 = fmaxf(mx1, __shfl_xor_sync(0xffffffffu, mx1, 1));
            mx1 = fmaxf(mx1, __shfl_xor_sync(0xffffffffu, mx1, 2));
            const float mn0 = fmaxf(m0, mx0), mn1 = fmaxf(m1, mx1);
            const float al0 = fexp2(m0 - mn0), al1 = fexp2(m1 - mn1);
            float s0 = 0.f, s1 = 0.f;
#pragma unroll
            for (int nt = 0; nt < 8; nt++) {
                accS[nt][0] = fexp2(accS[nt][0] - mn0);
                accS[nt][1] = fexp2(accS[nt][1] - mn0);
                accS[nt][2] = fexp2(accS[nt][2] - mn1);
                accS[nt][3] = fexp2(accS[nt][3] - mn1);
                s0 += accS[nt][0] + accS[nt][1];
                s1 += accS[nt][2] + accS[nt][3];
            }
            s0 += __shfl_xor_sync(0xffffffffu, s0, 1);
            s0 += __shfl_xor_sync(0xffffffffu, s0, 2);
            s1 += __shfl_xor_sync(0xffffffffu, s1, 1);
            s1 += __shfl_xor_sync(0xffffffffu, s1, 2);
            l0 = l0*al0 + s0;  l1 = l1*al1 + s1;
            m0 = mn0;          m1 = mn1;
#pragma unroll
            for (int nt = 0; nt < 8; nt++) {
                accO[nt][0] *= al0; accO[nt][1] *= al0;
                accO[nt][2] *= al1; accO[nt][3] *= al1;
            }

            // ---- O += P V ----
            const uint32_t vb = s_v + buf*FKSZB;
            const int g2 = lane >> 3, li = lane & 7;
#pragma unroll
            for (int ks2 = 0; ks2 < 4; ks2++) {
                unsigned aP[4];
                aP[0] = pack_h2(accS[2*ks2][0],     accS[2*ks2][1]);
                aP[1] = pack_h2(accS[2*ks2][2],     accS[2*ks2][3]);
                aP[2] = pack_h2(accS[2*ks2 + 1][0], accS[2*ks2 + 1][1]);
                aP[3] = pack_h2(accS[2*ks2 + 1][2], accS[2*ks2 + 1][3]);
#pragma unroll
                for (int ntp = 0; ntp < 4; ntp++) {
                    unsigned r[4];
                    const uint32_t addr = vb
                        + (uint32_t)((ks2*16 + (g2 & 1)*8 + li) * FQSTB
                                     + (ntp*16 + (g2 >> 1)*8) * 2);
                    ldsm4t(r, addr);
                    mma_f16(accO[2*ntp],     aP, r);
                    mma_f16(accO[2*ntp + 1], aP, r + 2);
                }
            }
        }
    }

    const float inv0 = 1.f / l0, inv1 = 1.f / l1;
    const int r0g = q0 + wm + lg, r1g = r0g + 8;
#pragma unroll
    for (int nt = 0; nt < 8; nt++) {
        const int col = nt*8 + 2*lc;
        *(unsigned*)(Ob + (size_t)r0g * D_MODEL + col) =
            pack_h2(accO[nt][0]*inv0, accO[nt][1]*inv0);
        *(unsigned*)(Ob + (size_t)r1g * D_MODEL + col) =
            pack_h2(accO[nt][2]*inv1, accO[nt][3]*inv1);
    }
}

// ===========================================================================
extern "C" void kernel_launch(void* const* d_in, const int* in_sizes, int n_in,
                              void* d_out, int out_size)
{
    const float* X  = (const float*)d_in[0];
    const float* Wq = (const float*)d_in[1];
    const float* bq = (const float*)d_in[2];
    const float* Wk = (const float*)d_in[3];
    const float* bk = (const float*)d_in[4];
    const float* Wv = (const float*)d_in[5];
    const float* bv = (const float*)d_in[6];
    const float* Wo = (const float*)d_in[7];
    const float* bo = (const float*)d_in[8];
    float* out = (float*)d_out;

    __half *x16, *wqkv, *wo16, *qkv, *ap;
    float* bqkv;
    cudaGetSymbolAddress((void**)&x16,  g_X16);
    cudaGetSymbolAddress((void**)&wqkv, g_Wqkv);
    cudaGetSymbolAddress((void**)&wo16, g_Wo16);
    cudaGetSymbolAddress((void**)&bqkv, g_Bqkv);
    cudaGetSymbolAddress((void**)&qkv,  g_QKV);
    cudaGetSymbolAddress((void**)&ap,   g_A16);
    const size_t WSZ = (size_t)D_MODEL * D_MODEL;

    cudaFuncSetAttribute(gemm_f16,  cudaFuncAttributeMaxDynamicSharedMemorySize, GEMM_SMEM);
    cudaFuncSetAttribute(flash_f16, cudaFuncAttributeMaxDynamicSharedMemorySize, FLASH_SMEM);

    cvtX<<<(size_t)MTOT * D_MODEL / (256*8), 256>>>((const float4*)X, x16);
    cvtW<<<WSZ / (256*8), 256>>>((const float4*)Wq, wqkv, 0);
    cvtW<<<WSZ / (256*8), 256>>>((const float4*)Wk, wqkv, 1024);
    cvtW<<<WSZ / (256*8), 256>>>((const float4*)Wv, wqkv, 2048);
    cvtX<<<WSZ / (256*8), 256>>>((const float4*)Wo, wo16);
    fuse_bias<<<NQKV/256, 256>>>(bq, bk, bv);
    rope_table<<<SEQ*512/256, 256>>>();

    // fused QKV projection: N = 3072
    gemm_f16<<<dim3(NQKV/128, MTOT/128), 256, GEMM_SMEM>>>(
        x16, wqkv, bqkv, nullptr, qkv, 1, 2048, NQKV, NQKV);

    flash_f16<<<dim3(SEQ/128, NHEADS, BATCH), 256, FLASH_SMEM>>>(qkv, ap);

    // output projection: N = 1024, fp32 out
    gemm_f16<<<dim3(D_MODEL/128, MTOT/128), 256, GEMM_SMEM>>>(
        ap, wo16, bo, out, nullptr, 0, 0, D_MODEL, D_MODEL);
}